// round 1
// baseline (speedup 1.0000x reference)
#include <cuda_runtime.h>
#include <cstdint>

#define Bb 32
#define Ll 512
#define Dd 512
#define Ss 8

// Scratch (device globals: allocation-free per harness rules)
__device__ float g_A1[(size_t)Bb * Ss * Ll * Dd];  // [b][k][i][e]  256 MiB
__device__ float g_P1[Bb * Ll * Ss];
__device__ float g_P2[Bb * Ll * Ss];
__device__ float g_Q1[Bb * Ll * Ss];
__device__ float g_Q2[Bb * Ll * Ss];

__device__ __forceinline__ float sigf(float x) {
    return __fdividef(1.0f, 1.0f + __expf(-x));
}

// ---------------------------------------------------------------------------
// K1: projections. One warp per row (arg1 rows then arg2 rows).
// P = row @ Wg_half, Q = row @ V_half  (S=8 outputs each).
// ---------------------------------------------------------------------------
__global__ void proj_kernel(const float* __restrict__ arg1,
                            const float* __restrict__ arg2,
                            const float* __restrict__ Wg,
                            const float* __restrict__ V) {
    int w = (blockIdx.x * blockDim.x + threadIdx.x) >> 5;
    int lane = threadIdx.x & 31;

    const float* src;
    int row, woff;
    float *outP, *outQ;
    if (w < Bb * Ll) {
        src = arg1; row = w; woff = 0; outP = g_P1; outQ = g_Q1;
    } else {
        src = arg2; row = w - Bb * Ll; woff = Dd; outP = g_P2; outQ = g_Q2;
    }

    float aw[8] = {0.f,0.f,0.f,0.f,0.f,0.f,0.f,0.f};
    float av[8] = {0.f,0.f,0.f,0.f,0.f,0.f,0.f,0.f};

    for (int d = lane; d < Dd; d += 32) {
        float x = src[(size_t)row * Dd + d];
        const float4* wp = reinterpret_cast<const float4*>(Wg + (size_t)(woff + d) * Ss);
        const float4* vp = reinterpret_cast<const float4*>(V  + (size_t)(woff + d) * Ss);
        float4 w0 = wp[0], w1 = wp[1];
        float4 v0 = vp[0], v1 = vp[1];
        aw[0] += x * w0.x; aw[1] += x * w0.y; aw[2] += x * w0.z; aw[3] += x * w0.w;
        aw[4] += x * w1.x; aw[5] += x * w1.y; aw[6] += x * w1.z; aw[7] += x * w1.w;
        av[0] += x * v0.x; av[1] += x * v0.y; av[2] += x * v0.z; av[3] += x * v0.w;
        av[4] += x * v1.x; av[5] += x * v1.y; av[6] += x * v1.z; av[7] += x * v1.w;
    }

#pragma unroll
    for (int s = 0; s < 8; s++) {
#pragma unroll
        for (int o = 16; o > 0; o >>= 1) {
            aw[s] += __shfl_xor_sync(0xffffffffu, aw[s], o);
            av[s] += __shfl_xor_sync(0xffffffffu, av[s], o);
        }
    }
    if (lane == 0) {
#pragma unroll
        for (int s = 0; s < 8; s++) {
            outP[(size_t)row * Ss + s] = aw[s];
            outQ[(size_t)row * Ss + s] = av[s];
        }
    }
}

// ---------------------------------------------------------------------------
// K2: A1[b,k] = arg1[b] (L x D) @ Mr[k] (D x D).
// 128x128 tile, K-chunk 8, 256 threads, 8x8 micro-tile per thread.
// ---------------------------------------------------------------------------
__global__ __launch_bounds__(256) void mr_gemm_kernel(const float* __restrict__ arg1,
                                                      const float* __restrict__ Mr) {
    __shared__ float Asm[8][132];   // [d][i], padded: conflict-free transpose store
    __shared__ float Bsm[8][128];   // [d][e]

    int t = threadIdx.x;
    int bk = blockIdx.z;
    int bb = bk >> 3;
    int k  = bk & 7;
    int i0 = blockIdx.y * 128;
    int e0 = blockIdx.x * 128;

    const float* Abase = arg1 + ((size_t)bb * Ll + i0) * Dd;
    const float* Bbase = Mr + (size_t)k * Dd * Dd + e0;

    int tx = t & 15, ty = t >> 4;
    int li = t >> 1, lc = (t & 1) * 4;    // A load: row li, 4 cols at lc
    int ld = t >> 5, le = (t & 31) * 4;   // B load: row ld, 4 cols at le

    float acc[8][8];
#pragma unroll
    for (int i = 0; i < 8; i++)
#pragma unroll
        for (int j = 0; j < 8; j++) acc[i][j] = 0.f;

    for (int d0 = 0; d0 < Dd; d0 += 8) {
        float4 avv = *reinterpret_cast<const float4*>(Abase + (size_t)li * Dd + d0 + lc);
        float4 bvv = *reinterpret_cast<const float4*>(Bbase + (size_t)(d0 + ld) * Dd + le);
        __syncthreads();
        Asm[lc + 0][li] = avv.x;
        Asm[lc + 1][li] = avv.y;
        Asm[lc + 2][li] = avv.z;
        Asm[lc + 3][li] = avv.w;
        *reinterpret_cast<float4*>(&Bsm[ld][le]) = bvv;
        __syncthreads();

#pragma unroll
        for (int d = 0; d < 8; d++) {
            float a[8], bf[8];
            *reinterpret_cast<float4*>(&a[0])  = *reinterpret_cast<float4*>(&Asm[d][ty * 4]);
            *reinterpret_cast<float4*>(&a[4])  = *reinterpret_cast<float4*>(&Asm[d][ty * 4 + 64]);
            *reinterpret_cast<float4*>(&bf[0]) = *reinterpret_cast<float4*>(&Bsm[d][tx * 4]);
            *reinterpret_cast<float4*>(&bf[4]) = *reinterpret_cast<float4*>(&Bsm[d][tx * 4 + 64]);
#pragma unroll
            for (int ii = 0; ii < 8; ii++)
#pragma unroll
                for (int jj = 0; jj < 8; jj++) acc[ii][jj] += a[ii] * bf[jj];
        }
    }

    float* Cbase = g_A1 + ((size_t)(bb * 8 + k) * Ll + i0) * Dd + e0;
#pragma unroll
    for (int ii = 0; ii < 8; ii++) {
        int gi = ty * 4 + (ii & 3) + ((ii >> 2) * 64);
#pragma unroll
        for (int jh = 0; jh < 2; jh++) {
            float4 v = make_float4(acc[ii][jh * 4 + 0], acc[ii][jh * 4 + 1],
                                   acc[ii][jh * 4 + 2], acc[ii][jh * 4 + 3]);
            *reinterpret_cast<float4*>(Cbase + (size_t)gi * Dd + tx * 4 + jh * 64) = v;
        }
    }
}

// ---------------------------------------------------------------------------
// K3: fused bi-GEMM (8 simultaneous k-planes) + gated epilogue.
// Tile: 32 i x 64 j, 256 threads; thread micro-tile 2i x 4j x 8k = 64 accums.
// ---------------------------------------------------------------------------
__global__ __launch_bounds__(256) void fused_kernel(const float* __restrict__ arg2,
                                                    const float* __restrict__ Bg,
                                                    const float* __restrict__ bvec,
                                                    const float* __restrict__ U,
                                                    float* __restrict__ out) {
    __shared__ float As[8][32][34];  // [k][e][i], padded (even stride for float2)
    __shared__ float Bs[32][68];     // [e][j],   padded (float4-aligned stride)

    int t  = threadIdx.x;
    int bb = blockIdx.z;
    int it = blockIdx.y;
    int jt = blockIdx.x;
    int tx = t & 15, ty = t >> 4;

    float acc[8][2][4];
#pragma unroll
    for (int k = 0; k < 8; k++)
#pragma unroll
        for (int a = 0; a < 2; a++)
#pragma unroll
            for (int c = 0; c < 4; c++) acc[k][a][c] = 0.f;

    for (int e0 = 0; e0 < Dd; e0 += 32) {
        __syncthreads();
        // Load A1 chunk: 8k x 32i x 32e, transposed into [k][e][i]
#pragma unroll
        for (int m = 0; m < 8; m++) {
            int r  = t + 256 * m;
            int e4 = r & 7;
            int i  = (r >> 3) & 31;
            int k  = r >> 8;
            float4 v = *reinterpret_cast<const float4*>(
                g_A1 + ((size_t)(bb * 8 + k) * Ll + it * 32 + i) * Dd + e0 + e4 * 4);
            As[k][e4 * 4 + 0][i] = v.x;
            As[k][e4 * 4 + 1][i] = v.y;
            As[k][e4 * 4 + 2][i] = v.z;
            As[k][e4 * 4 + 3][i] = v.w;
        }
        // Load arg2 chunk: 64j x 32e, transposed into [e][j]
#pragma unroll
        for (int m = 0; m < 2; m++) {
            int r  = t + 256 * m;
            int e4 = r & 7;
            int j  = r >> 3;
            float4 v = *reinterpret_cast<const float4*>(
                arg2 + ((size_t)bb * Ll + jt * 64 + j) * Dd + e0 + e4 * 4);
            Bs[e4 * 4 + 0][j] = v.x;
            Bs[e4 * 4 + 1][j] = v.y;
            Bs[e4 * 4 + 2][j] = v.z;
            Bs[e4 * 4 + 3][j] = v.w;
        }
        __syncthreads();

#pragma unroll 8
        for (int e = 0; e < 32; e++) {
            float4 bj = *reinterpret_cast<const float4*>(&Bs[e][tx * 4]);
#pragma unroll
            for (int k = 0; k < 8; k++) {
                float2 ai = *reinterpret_cast<const float2*>(&As[k][e][ty * 2]);
                acc[k][0][0] += ai.x * bj.x;
                acc[k][0][1] += ai.x * bj.y;
                acc[k][0][2] += ai.x * bj.z;
                acc[k][0][3] += ai.x * bj.w;
                acc[k][1][0] += ai.y * bj.x;
                acc[k][1][1] += ai.y * bj.y;
                acc[k][1][2] += ai.y * bj.z;
                acc[k][1][3] += ai.y * bj.w;
            }
        }
    }

    // Epilogue
    float Bgv[8], Uv[8], bvv[8];
    *reinterpret_cast<float4*>(&Bgv[0]) = *reinterpret_cast<const float4*>(&Bg[0]);
    *reinterpret_cast<float4*>(&Bgv[4]) = *reinterpret_cast<const float4*>(&Bg[4]);
    *reinterpret_cast<float4*>(&Uv[0])  = *reinterpret_cast<const float4*>(&U[0]);
    *reinterpret_cast<float4*>(&Uv[4])  = *reinterpret_cast<const float4*>(&U[4]);
    *reinterpret_cast<float4*>(&bvv[0]) = *reinterpret_cast<const float4*>(&bvec[0]);
    *reinterpret_cast<float4*>(&bvv[4]) = *reinterpret_cast<const float4*>(&bvec[4]);
    float bU = 0.f;
#pragma unroll
    for (int k = 0; k < 8; k++) bU += bvv[k] * Uv[k];

    int gj0 = jt * 64 + tx * 4;
#pragma unroll
    for (int ii = 0; ii < 2; ii++) {
        int gi = it * 32 + ty * 2 + ii;
        float p1[8], q1[8];
        const float* p1p = g_P1 + ((size_t)bb * Ll + gi) * Ss;
        const float* q1p = g_Q1 + ((size_t)bb * Ll + gi) * Ss;
        *reinterpret_cast<float4*>(&p1[0]) = *reinterpret_cast<const float4*>(p1p);
        *reinterpret_cast<float4*>(&p1[4]) = *reinterpret_cast<const float4*>(p1p + 4);
        *reinterpret_cast<float4*>(&q1[0]) = *reinterpret_cast<const float4*>(q1p);
        *reinterpret_cast<float4*>(&q1[4]) = *reinterpret_cast<const float4*>(q1p + 4);

        float o[4];
#pragma unroll
        for (int jj = 0; jj < 4; jj++) {
            int gj = gj0 + jj;
            float p2[8], q2[8];
            const float* p2p = g_P2 + ((size_t)bb * Ll + gj) * Ss;
            const float* q2p = g_Q2 + ((size_t)bb * Ll + gj) * Ss;
            *reinterpret_cast<float4*>(&p2[0]) = *reinterpret_cast<const float4*>(p2p);
            *reinterpret_cast<float4*>(&p2[4]) = *reinterpret_cast<const float4*>(p2p + 4);
            *reinterpret_cast<float4*>(&q2[0]) = *reinterpret_cast<const float4*>(q2p);
            *reinterpret_cast<float4*>(&q2[4]) = *reinterpret_cast<const float4*>(q2p + 4);

            float sc = bU;
#pragma unroll
            for (int k = 0; k < 8; k++) {
                float g = sigf(p1[k] + p2[k] + Bgv[k]);
                float s = sigf(q1[k] + q2[k]);
                sc += Uv[k] * (acc[k][ii][jj] * g + s * (1.0f - g));
            }
            o[jj] = sigf(sc);
        }
        *reinterpret_cast<float4*>(out + ((size_t)bb * Ll + gi) * Ll + gj0) =
            make_float4(o[0], o[1], o[2], o[3]);
    }
}

// ---------------------------------------------------------------------------
extern "C" void kernel_launch(void* const* d_in, const int* in_sizes, int n_in,
                              void* d_out, int out_size) {
    const float* arg1 = (const float*)d_in[0];
    const float* arg2 = (const float*)d_in[1];
    const float* Wg   = (const float*)d_in[2];
    const float* Bg   = (const float*)d_in[3];
    const float* Mr   = (const float*)d_in[4];
    const float* V    = (const float*)d_in[5];
    const float* bvec = (const float*)d_in[6];
    const float* U    = (const float*)d_in[7];
    float* out = (float*)d_out;

    // K1: 2*B*L rows, one warp each, 8 warps/block
    proj_kernel<<<(2 * Bb * Ll) / 8, 256>>>(arg1, arg2, Wg, V);

    // K2: per (b,k): 512x512x512 GEMM in 128x128 tiles
    dim3 g2(Dd / 128, Ll / 128, Bb * Ss);
    mr_gemm_kernel<<<g2, 256>>>(arg1, Mr);

    // K3: fused bi-GEMM + epilogue, 32x64 (i,j) tiles
    dim3 g3(Ll / 64, Ll / 32, Bb);
    fused_kernel<<<g3, 256>>>(arg2, Bg, bvec, U, out);
}